// round 1
// baseline (speedup 1.0000x reference)
#include <cuda_runtime.h>
#include <cuda_bf16.h>
#include <math.h>

#define DIM    1024
#define MLPD   4096
#define DSTATE 16
#define DCONV  4
#define HALF   1024
#define DINNER 2048
#define DTRANK 64
#define BSZ    2
#define SEQ    2048
#define NTOK   (BSZ * SEQ)   // 4096
#define LN_EPS 1e-5f

// ---------------- scratch (device globals; no allocations allowed) ----------
__device__ float g_xn1[NTOK * DIM];       // LN1 out
__device__ float g_xz[NTOK * DINNER];     // in_proj out
__device__ float g_u[NTOK * HALF];        // conv_x + silu ("u")
__device__ float g_y[NTOK * DINNER];      // [scan_out | zc] concat
__device__ float g_xdbl[NTOK * 96];       // x_proj out (dt | B | C)
__device__ float g_delta[NTOK * HALF];    // softplus(dt_proj)
__device__ float g_res1[NTOK * DIM];      // x + mixer(x)
__device__ float g_ln2[NTOK * DIM];       // LN2 out
__device__ float g_mlp[NTOK * MLPD];      // gelu(mlp1)

// ---------------- LayerNorm: one block per row of 1024 ----------------------
__global__ __launch_bounds__(256) void ln_kernel(
    const float* __restrict__ in, float* __restrict__ out,
    const float* __restrict__ g, const float* __restrict__ b)
{
    int row = blockIdx.x;
    const float* x = in + (size_t)row * DIM;
    float4 v = *(const float4*)(x + threadIdx.x * 4);
    float s  = v.x + v.y + v.z + v.w;
    float sq = v.x*v.x + v.y*v.y + v.z*v.z + v.w*v.w;
    #pragma unroll
    for (int o = 16; o; o >>= 1) {
        s  += __shfl_xor_sync(0xffffffffu, s,  o);
        sq += __shfl_xor_sync(0xffffffffu, sq, o);
    }
    __shared__ float ss[8], sqq[8];
    int w = threadIdx.x >> 5;
    if ((threadIdx.x & 31) == 0) { ss[w] = s; sqq[w] = sq; }
    __syncthreads();
    s = 0.f; sq = 0.f;
    #pragma unroll
    for (int i = 0; i < 8; i++) { s += ss[i]; sq += sqq[i]; }
    float mu = s * (1.0f / DIM);
    float var = sq * (1.0f / DIM) - mu * mu;
    float rs = rsqrtf(var + LN_EPS);
    float4 gg = *(const float4*)(g + threadIdx.x * 4);
    float4 bb = *(const float4*)(b + threadIdx.x * 4);
    float4 o4;
    o4.x = (v.x - mu) * rs * gg.x + bb.x;
    o4.y = (v.y - mu) * rs * gg.y + bb.y;
    o4.z = (v.z - mu) * rs * gg.z + bb.z;
    o4.w = (v.w - mu) * rs * gg.w + bb.w;
    *(float4*)(out + (size_t)row * DIM + threadIdx.x * 4) = o4;
}

// ---------------- depthwise conv (K=4, pad L=1,R=2) + SiLU on both halves ---
__device__ __forceinline__ float silu(float v) { return v / (1.0f + expf(-v)); }

__global__ __launch_bounds__(256) void conv_silu_kernel(
    const float* __restrict__ xz,
    const float* __restrict__ wx, const float* __restrict__ bx,
    const float* __restrict__ wz, const float* __restrict__ bz,
    float* __restrict__ u, float* __restrict__ y)
{
    int idx = blockIdx.x * blockDim.x + threadIdx.x;  // NTOK*HALF threads
    int d = idx & (HALF - 1);
    int token = idx >> 10;
    int b = token >> 11;          // SEQ = 2048
    int l = token & (SEQ - 1);
    float accx = bx[d], accz = bz[d];
    #pragma unroll
    for (int k = 0; k < DCONV; k++) {
        int lp = l - 1 + k;
        if (lp >= 0 && lp < SEQ) {
            const float* row = xz + ((size_t)(b * SEQ + lp)) * DINNER;
            accx += row[d]        * wx[d * DCONV + k];
            accz += row[HALF + d] * wz[d * DCONV + k];
        }
    }
    u[(size_t)token * HALF + d] = silu(accx);
    y[(size_t)token * DINNER + HALF + d] = silu(accz);
}

// ---------------- generic tiled SGEMM: C = A(MxK, lda) * B(NxK)^T + epi -----
// MODE 0: C=acc   1: softplus(acc+bias[n])   2: acc+resid   3: gelu(acc+bias[n])
// MODE 4: acc+bias[n]+resid
template<int MODE>
__global__ __launch_bounds__(256) void gemm_kernel(
    const float* __restrict__ A, const float* __restrict__ B,
    float* __restrict__ C, int M, int N, int K, int lda,
    const float* __restrict__ bias, const float* __restrict__ resid)
{
    __shared__ float As[8][132];
    __shared__ float Bs[8][132];
    int tid = threadIdx.x;
    int row0 = blockIdx.y * 128;
    int col0 = blockIdx.x * 128;

    int lrow = tid >> 1;            // 0..127
    int lk4  = (tid & 1) * 4;       // 0 or 4
    const float* Aptr = A + (size_t)(row0 + lrow) * lda + lk4;
    const float* Bptr = B + (size_t)(col0 + lrow) * K + lk4;
    bool bvalid = (col0 + lrow) < N;

    int tx = tid & 15, ty = tid >> 4;
    float acc[8][8];
    #pragma unroll
    for (int i = 0; i < 8; i++)
        #pragma unroll
        for (int j = 0; j < 8; j++) acc[i][j] = 0.f;

    for (int k0 = 0; k0 < K; k0 += 8) {
        float4 av = *(const float4*)(Aptr + k0);
        float4 bv = bvalid ? *(const float4*)(Bptr + k0) : make_float4(0.f,0.f,0.f,0.f);
        As[lk4+0][lrow]=av.x; As[lk4+1][lrow]=av.y; As[lk4+2][lrow]=av.z; As[lk4+3][lrow]=av.w;
        Bs[lk4+0][lrow]=bv.x; Bs[lk4+1][lrow]=bv.y; Bs[lk4+2][lrow]=bv.z; Bs[lk4+3][lrow]=bv.w;
        __syncthreads();
        #pragma unroll
        for (int kk = 0; kk < 8; kk++) {
            float4 a0 = *(const float4*)&As[kk][ty * 8];
            float4 a1 = *(const float4*)&As[kk][ty * 8 + 4];
            float4 b0 = *(const float4*)&Bs[kk][tx * 8];
            float4 b1 = *(const float4*)&Bs[kk][tx * 8 + 4];
            float ar[8] = {a0.x,a0.y,a0.z,a0.w,a1.x,a1.y,a1.z,a1.w};
            float br[8] = {b0.x,b0.y,b0.z,b0.w,b1.x,b1.y,b1.z,b1.w};
            #pragma unroll
            for (int i = 0; i < 8; i++)
                #pragma unroll
                for (int j = 0; j < 8; j++) acc[i][j] += ar[i] * br[j];
        }
        __syncthreads();
    }

    #pragma unroll
    for (int i = 0; i < 8; i++) {
        int m = row0 + ty * 8 + i;
        #pragma unroll
        for (int j = 0; j < 8; j++) {
            int n = col0 + tx * 8 + j;
            if (n < N) {
                float v = acc[i][j];
                if (MODE == 1) {
                    v += bias[n];
                    v = (v > 20.f) ? v : log1pf(expf(v));
                } else if (MODE == 2) {
                    v += resid[(size_t)m * N + n];
                } else if (MODE == 3) {
                    v += bias[n];
                    v = 0.5f * v * (1.0f + erff(v * 0.70710678118654752f));
                } else if (MODE == 4) {
                    v += bias[n] + resid[(size_t)m * N + n];
                }
                C[(size_t)m * N + n] = v;
            }
        }
    }
}

// ---------------- selective scan: 16 lanes per (b,d) channel ----------------
__global__ __launch_bounds__(256) void scan_kernel(
    const float* __restrict__ delta, const float* __restrict__ u,
    const float* __restrict__ xdbl, const float* __restrict__ A_log,
    const float* __restrict__ Dp, float* __restrict__ y)
{
    int gt = blockIdx.x * blockDim.x + threadIdx.x;
    int c = gt >> 4;               // channel 0..2047
    int n = gt & 15;               // state index
    int b = c >> 10;               // batch
    int d = c & (HALF - 1);

    float a  = -expf(A_log[d * DSTATE + n]);
    float Dd = Dp[d];
    float h = 0.f;

    const float* dptr = delta + (size_t)b * SEQ * HALF + d;
    const float* uptr = u     + (size_t)b * SEQ * HALF + d;
    const float* bptr = xdbl  + (size_t)b * SEQ * 96 + DTRANK + n;
    const float* cptr = xdbl  + (size_t)b * SEQ * 96 + DTRANK + DSTATE + n;
    float* yptr = y + (size_t)b * SEQ * DINNER + d;

    float dl = dptr[0], uv = uptr[0], Bv = bptr[0], Cv = cptr[0];
    for (int t = 0; t < SEQ; t++) {
        float dl_n = dl, uv_n = uv, Bv_n = Bv, Cv_n = Cv;
        if (t + 1 < SEQ) {
            int oh = (t + 1) * HALF, o9 = (t + 1) * 96;
            dl_n = dptr[oh]; uv_n = uptr[oh];
            Bv_n = bptr[o9]; Cv_n = cptr[o9];
        }
        float dA = expf(dl * a);
        h = dA * h + (dl * Bv) * uv;
        float p = h * Cv;
        p += __shfl_xor_sync(0xffffffffu, p, 8);
        p += __shfl_xor_sync(0xffffffffu, p, 4);
        p += __shfl_xor_sync(0xffffffffu, p, 2);
        p += __shfl_xor_sync(0xffffffffu, p, 1);
        if (n == 0) yptr[(size_t)t * DINNER] = p + uv * Dd;
        dl = dl_n; uv = uv_n; Bv = Bv_n; Cv = Cv_n;
    }
}

// ---------------- launch --------------------------------------------------
extern "C" void kernel_launch(void* const* d_in, const int* in_sizes, int n_in,
                              void* d_out, int out_size)
{
    const float* x         = (const float*)d_in[0];
    const float* ln1_g     = (const float*)d_in[1];
    const float* ln1_b     = (const float*)d_in[2];
    const float* in_proj_w = (const float*)d_in[3];
    const float* conv_x_w  = (const float*)d_in[4];
    const float* conv_x_b  = (const float*)d_in[5];
    const float* conv_z_w  = (const float*)d_in[6];
    const float* conv_z_b  = (const float*)d_in[7];
    const float* x_proj_w  = (const float*)d_in[8];
    const float* dt_proj_w = (const float*)d_in[9];
    const float* dt_proj_b = (const float*)d_in[10];
    const float* A_log     = (const float*)d_in[11];
    const float* Dp        = (const float*)d_in[12];
    const float* out_proj_w= (const float*)d_in[13];
    const float* ln2_g     = (const float*)d_in[14];
    const float* ln2_b     = (const float*)d_in[15];
    const float* mlp_w1    = (const float*)d_in[16];
    const float* mlp_b1    = (const float*)d_in[17];
    const float* mlp_w2    = (const float*)d_in[18];
    const float* mlp_b2    = (const float*)d_in[19];
    float* out = (float*)d_out;

    float *xn1, *xz, *u, *y, *xdbl, *delta, *res1, *ln2o, *mlp;
    cudaGetSymbolAddress((void**)&xn1,  g_xn1);
    cudaGetSymbolAddress((void**)&xz,   g_xz);
    cudaGetSymbolAddress((void**)&u,    g_u);
    cudaGetSymbolAddress((void**)&y,    g_y);
    cudaGetSymbolAddress((void**)&xdbl, g_xdbl);
    cudaGetSymbolAddress((void**)&delta,g_delta);
    cudaGetSymbolAddress((void**)&res1, g_res1);
    cudaGetSymbolAddress((void**)&ln2o, g_ln2);
    cudaGetSymbolAddress((void**)&mlp,  g_mlp);

    // 1. LN1
    ln_kernel<<<NTOK, 256>>>(x, xn1, ln1_g, ln1_b);
    // 2. in_proj: [4096,1024] x [2048,1024]^T -> [4096,2048]
    gemm_kernel<0><<<dim3(DINNER/128, NTOK/128), 256>>>(
        xn1, in_proj_w, xz, NTOK, DINNER, DIM, DIM, nullptr, nullptr);
    // 3. conv + silu (writes u and zc directly into y[:,1024:])
    conv_silu_kernel<<<(NTOK*HALF)/256, 256>>>(xz, conv_x_w, conv_x_b,
                                               conv_z_w, conv_z_b, u, y);
    // 4. x_proj: [4096,1024] x [96,1024]^T -> [4096,96]
    gemm_kernel<0><<<dim3(1, NTOK/128), 256>>>(
        u, x_proj_w, xdbl, NTOK, 96, HALF, HALF, nullptr, nullptr);
    // 5. dt_proj + softplus: [4096,64](lda=96) x [1024,64]^T -> [4096,1024]
    gemm_kernel<1><<<dim3(HALF/128, NTOK/128), 256>>>(
        xdbl, dt_proj_w, delta, NTOK, HALF, DTRANK, 96, dt_proj_b, nullptr);
    // 6. selective scan -> y[:, :1024]
    scan_kernel<<<(BSZ*HALF*DSTATE)/256, 256>>>(delta, u, xdbl, A_log, Dp, y);
    // 7. out_proj + residual: [4096,2048] x [1024,2048]^T + x -> res1
    gemm_kernel<2><<<dim3(DIM/128, NTOK/128), 256>>>(
        y, out_proj_w, res1, NTOK, DIM, DINNER, DINNER, nullptr, x);
    // 8. LN2
    ln_kernel<<<NTOK, 256>>>(res1, ln2o, ln2_g, ln2_b);
    // 9. mlp1 + gelu: [4096,1024] x [4096,1024]^T -> [4096,4096]
    gemm_kernel<3><<<dim3(MLPD/128, NTOK/128), 256>>>(
        ln2o, mlp_w1, mlp, NTOK, MLPD, DIM, DIM, mlp_b1, nullptr);
    // 10. mlp2 + bias + residual -> out
    gemm_kernel<4><<<dim3(DIM/128, NTOK/128), 256>>>(
        mlp, mlp_w2, out, NTOK, DIM, MLPD, MLPD, mlp_b2, res1);
}

// round 3
// speedup vs baseline: 2.4135x; 2.4135x over previous
#include <cuda_runtime.h>
#include <cuda_bf16.h>
#include <math.h>
#include <stdint.h>

#define DIM    1024
#define MLPD   4096
#define DSTATE 16
#define DCONV  4
#define HALF   1024
#define DINNER 2048
#define DTRANK 64
#define BSZ    2
#define SEQ    2048
#define NTOK   (BSZ * SEQ)   // 4096
#define LN_EPS 1e-5f

// ---------------- scratch (device globals; no allocations allowed) ----------
__device__ float g_xn1[NTOK * DIM];
__device__ float g_xz[NTOK * DINNER];
__device__ float g_u[NTOK * HALF];
__device__ float g_y[NTOK * DINNER];
__device__ float g_xdbl[NTOK * 96];
__device__ float g_delta[NTOK * HALF];
__device__ float g_res1[NTOK * DIM];
__device__ float g_ln2[NTOK * DIM];
__device__ float g_mlp[NTOK * MLPD];

// ======================= helpers ============================================
__device__ __forceinline__ uint32_t smem_u32(const void* p) {
    uint32_t a;
    asm("{ .reg .u64 t; cvta.to.shared.u64 t, %1; cvt.u32.u64 %0, t; }"
        : "=r"(a) : "l"(p));
    return a;
}
__device__ __forceinline__ void cp16(uint32_t dst, const void* src) {
    asm volatile("cp.async.cg.shared.global [%0], [%1], 16;"
                 :: "r"(dst), "l"(src) : "memory");
}
__device__ __forceinline__ void cp16z(uint32_t dst, const void* src, int sz) {
    asm volatile("cp.async.cg.shared.global [%0], [%1], 16, %2;"
                 :: "r"(dst), "l"(src), "r"(sz) : "memory");
}
#define CP_COMMIT() asm volatile("cp.async.commit_group;" ::: "memory")
#define CP_WAIT2()  asm volatile("cp.async.wait_group 2;" ::: "memory")

__device__ __forceinline__ uint32_t f2tf32(float f) {
    uint32_t r;
    asm("cvt.rna.tf32.f32 %0, %1;" : "=r"(r) : "f"(f));
    return r;
}
__device__ __forceinline__ void mma_tf32(float* c, const uint32_t* a, const uint32_t* b) {
    asm volatile(
        "mma.sync.aligned.m16n8k8.row.col.f32.tf32.tf32.f32 "
        "{%0,%1,%2,%3}, {%4,%5,%6,%7}, {%8,%9}, {%0,%1,%2,%3};"
        : "+f"(c[0]), "+f"(c[1]), "+f"(c[2]), "+f"(c[3])
        : "r"(a[0]), "r"(a[1]), "r"(a[2]), "r"(a[3]), "r"(b[0]), "r"(b[1]));
}

// ======================= TF32 MMA GEMM ======================================
// C[M,N] = A[M,K](lda) * B[N,K]^T. M%128==0, K%32==0, N%32==0.
// MODE 0: none  1: softplus(+bias)  2: +resid  3: gelu(+bias)  4: +bias+resid
#define PITCH 36
#define STG_FLOATS (2 * 128 * PITCH)          // As + Bs per stage
#define GEMM_SMEM  (3 * STG_FLOATS * 4)       // 110592 bytes

template<int MODE>
__global__ __launch_bounds__(256) void gemm_mma(
    const float* __restrict__ A, const float* __restrict__ B,
    float* __restrict__ C, int N, int K, int lda,
    const float* __restrict__ bias, const float* __restrict__ resid)
{
    extern __shared__ float sm[];
    const int tid = threadIdx.x;
    const int wid = tid >> 5, lane = tid & 31;
    const int gid = lane >> 2, t4 = lane & 3;
    const int wm = (wid >> 2) * 64, wn = (wid & 3) * 32;
    const int row0 = blockIdx.y * 128, col0 = blockIdx.x * 128;
    const int NC = K >> 5;

    uint32_t sbase = smem_u32(sm);

    // ---- async tile loader: chunk c -> stage s -------------------------
    auto load_chunk = [&](int c, int s) {
        uint32_t As = sbase + (uint32_t)(s * STG_FLOATS) * 4;
        uint32_t Bs = As + 128 * PITCH * 4;
        int k0 = c * 32;
        #pragma unroll
        for (int i = 0; i < 4; i++) {
            int idx = tid + 256 * i;
            int r = idx >> 3, c4 = (idx & 7) << 2;
            cp16(As + (uint32_t)(r * PITCH + c4) * 4,
                 A + (size_t)(row0 + r) * lda + k0 + c4);
        }
        #pragma unroll
        for (int i = 0; i < 4; i++) {
            int idx = tid + 256 * i;
            int r = idx >> 3, c4 = (idx & 7) << 2;
            int brow = col0 + r;
            const float* src = B + (size_t)(brow < N ? brow : 0) * K + k0 + c4;
            cp16z(Bs + (uint32_t)(r * PITCH + c4) * 4, src, brow < N ? 16 : 0);
        }
    };

    float acc[4][4][4];
    #pragma unroll
    for (int i = 0; i < 4; i++)
        #pragma unroll
        for (int j = 0; j < 4; j++)
            #pragma unroll
            for (int q = 0; q < 4; q++) acc[i][j][q] = 0.f;

    load_chunk(0, 0); CP_COMMIT();
    if (NC > 1) load_chunk(1, 1);
    CP_COMMIT();

    for (int c = 0; c < NC; c++) {
        if (c + 2 < NC) load_chunk(c + 2, (c + 2) % 3);
        CP_COMMIT();
        CP_WAIT2();
        __syncthreads();

        const float* As = sm + (c % 3) * STG_FLOATS;
        const float* Bs = As + 128 * PITCH;
        #pragma unroll
        for (int k8 = 0; k8 < 4; k8++) {
            uint32_t af[4][4], bf[4][2];
            #pragma unroll
            for (int mt = 0; mt < 4; mt++) {
                int mr = wm + mt * 16 + gid;
                int kc = k8 * 8 + t4;
                af[mt][0] = f2tf32(As[mr * PITCH + kc]);
                af[mt][1] = f2tf32(As[(mr + 8) * PITCH + kc]);
                af[mt][2] = f2tf32(As[mr * PITCH + kc + 4]);
                af[mt][3] = f2tf32(As[(mr + 8) * PITCH + kc + 4]);
            }
            #pragma unroll
            for (int nt = 0; nt < 4; nt++) {
                int nr = wn + nt * 8 + gid;
                int kc = k8 * 8 + t4;
                bf[nt][0] = f2tf32(Bs[nr * PITCH + kc]);
                bf[nt][1] = f2tf32(Bs[nr * PITCH + kc + 4]);
            }
            #pragma unroll
            for (int mt = 0; mt < 4; mt++)
                #pragma unroll
                for (int nt = 0; nt < 4; nt++)
                    mma_tf32(acc[mt][nt], af[mt], bf[nt]);
        }
        __syncthreads();
    }

    // ---- epilogue ------------------------------------------------------
    #pragma unroll
    for (int mt = 0; mt < 4; mt++) {
        #pragma unroll
        for (int r2 = 0; r2 < 2; r2++) {
            int m = row0 + wm + mt * 16 + gid + r2 * 8;
            #pragma unroll
            for (int nt = 0; nt < 4; nt++) {
                int n = col0 + wn + nt * 8 + 2 * t4;
                if (n < N) {
                    float v0 = acc[mt][nt][r2 * 2];
                    float v1 = acc[mt][nt][r2 * 2 + 1];
                    if (MODE == 1 || MODE == 3 || MODE == 4) {
                        v0 += bias[n]; v1 += bias[n + 1];
                    }
                    if (MODE == 1) {
                        v0 = (v0 > 20.f) ? v0 : log1pf(expf(v0));
                        v1 = (v1 > 20.f) ? v1 : log1pf(expf(v1));
                    }
                    if (MODE == 3) {
                        const float kq = 0.70710678118654752f;
                        v0 = 0.5f * v0 * (1.f + erff(v0 * kq));
                        v1 = 0.5f * v1 * (1.f + erff(v1 * kq));
                    }
                    if (MODE == 2 || MODE == 4) {
                        const float* rp = resid + (size_t)m * N + n;
                        v0 += rp[0]; v1 += rp[1];
                    }
                    *(float2*)(C + (size_t)m * N + n) = make_float2(v0, v1);
                }
            }
        }
    }
}

// ======================= LayerNorm ==========================================
__global__ __launch_bounds__(256) void ln_kernel(
    const float* __restrict__ in, float* __restrict__ out,
    const float* __restrict__ g, const float* __restrict__ b)
{
    int row = blockIdx.x;
    const float* x = in + (size_t)row * DIM;
    float4 v = *(const float4*)(x + threadIdx.x * 4);
    float s  = v.x + v.y + v.z + v.w;
    float sq = v.x*v.x + v.y*v.y + v.z*v.z + v.w*v.w;
    #pragma unroll
    for (int o = 16; o; o >>= 1) {
        s  += __shfl_xor_sync(0xffffffffu, s,  o);
        sq += __shfl_xor_sync(0xffffffffu, sq, o);
    }
    __shared__ float ss[8], sqq[8];
    int w = threadIdx.x >> 5;
    if ((threadIdx.x & 31) == 0) { ss[w] = s; sqq[w] = sq; }
    __syncthreads();
    s = 0.f; sq = 0.f;
    #pragma unroll
    for (int i = 0; i < 8; i++) { s += ss[i]; sq += sqq[i]; }
    float mu = s * (1.0f / DIM);
    float var = sq * (1.0f / DIM) - mu * mu;
    float rs = rsqrtf(var + LN_EPS);
    float4 gg = *(const float4*)(g + threadIdx.x * 4);
    float4 bb = *(const float4*)(b + threadIdx.x * 4);
    float4 o4;
    o4.x = (v.x - mu) * rs * gg.x + bb.x;
    o4.y = (v.y - mu) * rs * gg.y + bb.y;
    o4.z = (v.z - mu) * rs * gg.z + bb.z;
    o4.w = (v.w - mu) * rs * gg.w + bb.w;
    *(float4*)(out + (size_t)row * DIM + threadIdx.x * 4) = o4;
}

// ---------------- depthwise conv + SiLU -------------------------------------
__device__ __forceinline__ float silu(float v) { return v / (1.0f + expf(-v)); }

__global__ __launch_bounds__(256) void conv_silu_kernel(
    const float* __restrict__ xz,
    const float* __restrict__ wx, const float* __restrict__ bx,
    const float* __restrict__ wz, const float* __restrict__ bz,
    float* __restrict__ u, float* __restrict__ y)
{
    int idx = blockIdx.x * blockDim.x + threadIdx.x;
    int d = idx & (HALF - 1);
    int token = idx >> 10;
    int b = token >> 11;
    int l = token & (SEQ - 1);
    float accx = bx[d], accz = bz[d];
    #pragma unroll
    for (int k = 0; k < DCONV; k++) {
        int lp = l - 1 + k;
        if (lp >= 0 && lp < SEQ) {
            const float* row = xz + ((size_t)(b * SEQ + lp)) * DINNER;
            accx += row[d]        * wx[d * DCONV + k];
            accz += row[HALF + d] * wz[d * DCONV + k];
        }
    }
    u[(size_t)token * HALF + d] = silu(accx);
    y[(size_t)token * DINNER + HALF + d] = silu(accz);
}

// ---------------- selective scan --------------------------------------------
__global__ __launch_bounds__(256) void scan_kernel(
    const float* __restrict__ delta, const float* __restrict__ u,
    const float* __restrict__ xdbl, const float* __restrict__ A_log,
    const float* __restrict__ Dp, float* __restrict__ y)
{
    int gt = blockIdx.x * blockDim.x + threadIdx.x;
    int c = gt >> 4;
    int n = gt & 15;
    int b = c >> 10;
    int d = c & (HALF - 1);

    float a  = -expf(A_log[d * DSTATE + n]);
    float Dd = Dp[d];
    float h = 0.f;

    const float* dptr = delta + (size_t)b * SEQ * HALF + d;
    const float* uptr = u     + (size_t)b * SEQ * HALF + d;
    const float* bptr = xdbl  + (size_t)b * SEQ * 96 + DTRANK + n;
    const float* cptr = xdbl  + (size_t)b * SEQ * 96 + DTRANK + DSTATE + n;
    float* yptr = y + (size_t)b * SEQ * DINNER + d;

    float dl = dptr[0], uv = uptr[0], Bv = bptr[0], Cv = cptr[0];
    for (int t = 0; t < SEQ; t++) {
        float dl_n = dl, uv_n = uv, Bv_n = Bv, Cv_n = Cv;
        if (t + 1 < SEQ) {
            int oh = (t + 1) * HALF, o9 = (t + 1) * 96;
            dl_n = dptr[oh]; uv_n = uptr[oh];
            Bv_n = bptr[o9]; Cv_n = cptr[o9];
        }
        float dA = expf(dl * a);
        h = dA * h + (dl * Bv) * uv;
        float p = h * Cv;
        p += __shfl_xor_sync(0xffffffffu, p, 8);
        p += __shfl_xor_sync(0xffffffffu, p, 4);
        p += __shfl_xor_sync(0xffffffffu, p, 2);
        p += __shfl_xor_sync(0xffffffffu, p, 1);
        if (n == 0) yptr[(size_t)t * DINNER] = p + uv * Dd;
        dl = dl_n; uv = uv_n; Bv = Bv_n; Cv = Cv_n;
    }
}

// ======================= launch =============================================
extern "C" void kernel_launch(void* const* d_in, const int* in_sizes, int n_in,
                              void* d_out, int out_size)
{
    const float* x         = (const float*)d_in[0];
    const float* ln1_g     = (const float*)d_in[1];
    const float* ln1_b     = (const float*)d_in[2];
    const float* in_proj_w = (const float*)d_in[3];
    const float* conv_x_w  = (const float*)d_in[4];
    const float* conv_x_b  = (const float*)d_in[5];
    const float* conv_z_w  = (const float*)d_in[6];
    const float* conv_z_b  = (const float*)d_in[7];
    const float* x_proj_w  = (const float*)d_in[8];
    const float* dt_proj_w = (const float*)d_in[9];
    const float* dt_proj_b = (const float*)d_in[10];
    const float* A_log     = (const float*)d_in[11];
    const float* Dp        = (const float*)d_in[12];
    const float* out_proj_w= (const float*)d_in[13];
    const float* ln2_g     = (const float*)d_in[14];
    const float* ln2_b     = (const float*)d_in[15];
    const float* mlp_w1    = (const float*)d_in[16];
    const float* mlp_b1    = (const float*)d_in[17];
    const float* mlp_w2    = (const float*)d_in[18];
    const float* mlp_b2    = (const float*)d_in[19];
    float* out = (float*)d_out;

    float *xn1, *xz, *u, *y, *xdbl, *delta, *res1, *ln2o, *mlp;
    cudaGetSymbolAddress((void**)&xn1,  g_xn1);
    cudaGetSymbolAddress((void**)&xz,   g_xz);
    cudaGetSymbolAddress((void**)&u,    g_u);
    cudaGetSymbolAddress((void**)&y,    g_y);
    cudaGetSymbolAddress((void**)&xdbl, g_xdbl);
    cudaGetSymbolAddress((void**)&delta,g_delta);
    cudaGetSymbolAddress((void**)&res1, g_res1);
    cudaGetSymbolAddress((void**)&ln2o, g_ln2);
    cudaGetSymbolAddress((void**)&mlp,  g_mlp);

    cudaFuncSetAttribute(gemm_mma<0>, cudaFuncAttributeMaxDynamicSharedMemorySize, GEMM_SMEM);
    cudaFuncSetAttribute(gemm_mma<1>, cudaFuncAttributeMaxDynamicSharedMemorySize, GEMM_SMEM);
    cudaFuncSetAttribute(gemm_mma<2>, cudaFuncAttributeMaxDynamicSharedMemorySize, GEMM_SMEM);
    cudaFuncSetAttribute(gemm_mma<3>, cudaFuncAttributeMaxDynamicSharedMemorySize, GEMM_SMEM);
    cudaFuncSetAttribute(gemm_mma<4>, cudaFuncAttributeMaxDynamicSharedMemorySize, GEMM_SMEM);

    // 1. LN1
    ln_kernel<<<NTOK, 256>>>(x, xn1, ln1_g, ln1_b);
    // 2. in_proj: [4096,2048] = xn1[4096,1024] * W[2048,1024]^T
    gemm_mma<0><<<dim3(DINNER/128, NTOK/128), 256, GEMM_SMEM>>>(
        xn1, in_proj_w, xz, DINNER, DIM, DIM, nullptr, nullptr);
    // 3. conv + silu
    conv_silu_kernel<<<(NTOK*HALF)/256, 256>>>(xz, conv_x_w, conv_x_b,
                                               conv_z_w, conv_z_b, u, y);
    // 4. x_proj: [4096,96] = u * W[96,1024]^T
    gemm_mma<0><<<dim3(1, NTOK/128), 256, GEMM_SMEM>>>(
        u, x_proj_w, xdbl, 96, HALF, HALF, nullptr, nullptr);
    // 5. dt_proj + softplus: [4096,1024] = xdbl[:, :64](lda=96) * W[1024,64]^T
    gemm_mma<1><<<dim3(HALF/128, NTOK/128), 256, GEMM_SMEM>>>(
        xdbl, dt_proj_w, delta, HALF, DTRANK, 96, dt_proj_b, nullptr);
    // 6. selective scan
    scan_kernel<<<(BSZ*HALF*DSTATE)/256, 256>>>(delta, u, xdbl, A_log, Dp, y);
    // 7. out_proj + residual
    gemm_mma<2><<<dim3(DIM/128, NTOK/128), 256, GEMM_SMEM>>>(
        y, out_proj_w, res1, DIM, DINNER, DINNER, nullptr, x);
    // 8. LN2
    ln_kernel<<<NTOK, 256>>>(res1, ln2o, ln2_g, ln2_b);
    // 9. mlp1 + gelu
    gemm_mma<3><<<dim3(MLPD/128, NTOK/128), 256, GEMM_SMEM>>>(
        ln2o, mlp_w1, mlp, MLPD, DIM, DIM, mlp_b1, nullptr);
    // 10. mlp2 + bias + residual
    gemm_mma<4><<<dim3(DIM/128, NTOK/128), 256, GEMM_SMEM>>>(
        mlp, mlp_w2, out, DIM, MLPD, MLPD, mlp_b2, res1);
}

// round 4
// speedup vs baseline: 3.2076x; 1.3290x over previous
#include <cuda_runtime.h>
#include <cuda_fp16.h>
#include <math.h>
#include <stdint.h>

#define DIM    1024
#define MLPD   4096
#define DSTATE 16
#define DCONV  4
#define HALF   1024
#define DINNER 2048
#define DTRANK 64
#define BSZ    2
#define SEQ    2048
#define NTOK   (BSZ * SEQ)   // 4096
#define LN_EPS 1e-5f

// ---------------- scratch (device globals) ----------------------------------
__device__ float g_xz[NTOK * DINNER];
__device__ float g_u[NTOK * HALF];
__device__ float g_xdbl[NTOK * 96];
__device__ float g_delta[NTOK * HALF];
__device__ float g_res1[NTOK * DIM];

__device__ __half h_ln1[NTOK * DIM];
__device__ __half h_u[NTOK * HALF];
__device__ __half h_xdbl[NTOK * 96];
__device__ __half h_y[NTOK * DINNER];
__device__ __half h_ln2[NTOK * DIM];
__device__ __half h_mlp[NTOK * MLPD];

__device__ __half w16_in[DINNER * DIM];
__device__ __half w16_xp[96 * HALF];
__device__ __half w16_dt[HALF * DTRANK];
__device__ __half w16_out[DIM * DINNER];
__device__ __half w16_m1[MLPD * DIM];
__device__ __half w16_m2[DIM * MLPD];

// ======================= helpers ============================================
__device__ __forceinline__ uint32_t smem_u32(const void* p) {
    uint32_t a;
    asm("{ .reg .u64 t; cvta.to.shared.u64 t, %1; cvt.u32.u64 %0, t; }"
        : "=r"(a) : "l"(p));
    return a;
}
__device__ __forceinline__ void cp16(uint32_t dst, const void* src) {
    asm volatile("cp.async.cg.shared.global [%0], [%1], 16;"
                 :: "r"(dst), "l"(src) : "memory");
}
__device__ __forceinline__ void cp16z(uint32_t dst, const void* src, int sz) {
    asm volatile("cp.async.cg.shared.global [%0], [%1], 16, %2;"
                 :: "r"(dst), "l"(src), "r"(sz) : "memory");
}
#define CP_COMMIT() asm volatile("cp.async.commit_group;" ::: "memory")
#define CP_WAIT4()  asm volatile("cp.async.wait_group 4;" ::: "memory")

__device__ __forceinline__ void lm4(uint32_t& r0, uint32_t& r1, uint32_t& r2,
                                    uint32_t& r3, uint32_t addr) {
    asm volatile("ldmatrix.sync.aligned.m8n8.x4.shared.b16 {%0,%1,%2,%3}, [%4];"
                 : "=r"(r0), "=r"(r1), "=r"(r2), "=r"(r3) : "r"(addr));
}
__device__ __forceinline__ void mma_f16(float* c, const uint32_t* a, const uint32_t* b) {
    asm volatile(
        "mma.sync.aligned.m16n8k16.row.col.f32.f16.f16.f32 "
        "{%0,%1,%2,%3}, {%4,%5,%6,%7}, {%8,%9}, {%0,%1,%2,%3};"
        : "+f"(c[0]), "+f"(c[1]), "+f"(c[2]), "+f"(c[3])
        : "r"(a[0]), "r"(a[1]), "r"(a[2]), "r"(a[3]), "r"(b[0]), "r"(b[1]));
}

// ======================= fp16 MMA GEMM ======================================
// C[M,N] = A[M,K](lda halfs) * B[N,K]^T. M%128==0, K%32==0.
// MODE 0: none  1: softplus(+bias)  2: +resid  3: gelu(+bias)  4: +bias+resid
#define PITCH_H 40                              // halfs per 32-half row
#define STG_BYTES (2 * 128 * PITCH_H * 2)       // 20480
#define GEMM_SMEM (5 * STG_BYTES)               // 102400

template<int MODE, bool W32, bool W16>
__global__ __launch_bounds__(256, 2) void gemm_h(
    const __half* __restrict__ A, const __half* __restrict__ B,
    float* __restrict__ C, __half* __restrict__ C16,
    int N, int K, int lda,
    const float* __restrict__ bias, const float* __restrict__ resid)
{
    extern __shared__ char smraw[];
    const int tid = threadIdx.x;
    const int wid = tid >> 5, lane = tid & 31;
    const int gid = lane >> 2, t4 = lane & 3;
    const int wm = (wid >> 2) * 64, wn = (wid & 3) * 32;
    const int row0 = blockIdx.y * 128, col0 = blockIdx.x * 128;
    const int NC = K >> 5;
    uint32_t sbase = smem_u32(smraw);

    auto load_chunk = [&](int c, int s) {
        uint32_t As = sbase + (uint32_t)s * STG_BYTES;
        uint32_t Bs = As + 128 * PITCH_H * 2;
        int k0 = c * 32;
        #pragma unroll
        for (int i = 0; i < 2; i++) {
            int idx = tid + 256 * i;
            int r = idx >> 2, c8 = (idx & 3) * 8;
            cp16(As + (uint32_t)(r * PITCH_H + c8) * 2,
                 A + (size_t)(row0 + r) * lda + k0 + c8);
        }
        #pragma unroll
        for (int i = 0; i < 2; i++) {
            int idx = tid + 256 * i;
            int r = idx >> 2, c8 = (idx & 3) * 8;
            int brow = col0 + r;
            const __half* src = B + (size_t)(brow < N ? brow : 0) * K + k0 + c8;
            cp16z(Bs + (uint32_t)(r * PITCH_H + c8) * 2, src, brow < N ? 16 : 0);
        }
    };

    float acc[4][4][4];
    #pragma unroll
    for (int i = 0; i < 4; i++)
        #pragma unroll
        for (int j = 0; j < 4; j++)
            #pragma unroll
            for (int q = 0; q < 4; q++) acc[i][j][q] = 0.f;

    #pragma unroll
    for (int c = 0; c < 4; c++) {
        if (c < NC) load_chunk(c, c);
        CP_COMMIT();
    }

    // per-lane fragment addresses (byte offsets within a stage)
    const uint32_t aoff = (uint32_t)((wm + (lane & 15)) * PITCH_H + ((lane >> 4) << 3)) * 2;
    const uint32_t boff = 128 * PITCH_H * 2 +
        (uint32_t)((wn + ((lane >> 4) << 3) + (lane & 7)) * PITCH_H + (((lane >> 3) & 1) << 3)) * 2;

    for (int c = 0; c < NC; c++) {
        if (c + 4 < NC) load_chunk(c + 4, (c + 4) % 5);
        CP_COMMIT();
        CP_WAIT4();
        __syncthreads();

        uint32_t stage = sbase + (uint32_t)(c % 5) * STG_BYTES;
        #pragma unroll
        for (int k16 = 0; k16 < 2; k16++) {
            uint32_t kb = (uint32_t)(k16 * 16) * 2;
            uint32_t af[4][4], bf[4][2];
            #pragma unroll
            for (int mt = 0; mt < 4; mt++)
                lm4(af[mt][0], af[mt][1], af[mt][2], af[mt][3],
                    stage + aoff + kb + (uint32_t)(mt * 16 * PITCH_H) * 2);
            #pragma unroll
            for (int np = 0; np < 2; np++)
                lm4(bf[2*np][0], bf[2*np][1], bf[2*np+1][0], bf[2*np+1][1],
                    stage + boff + kb + (uint32_t)(np * 16 * PITCH_H) * 2);
            #pragma unroll
            for (int mt = 0; mt < 4; mt++)
                #pragma unroll
                for (int nt = 0; nt < 4; nt++)
                    mma_f16(acc[mt][nt], af[mt], bf[nt]);
        }
        __syncthreads();
    }

    // ---- epilogue ------------------------------------------------------
    #pragma unroll
    for (int mt = 0; mt < 4; mt++) {
        #pragma unroll
        for (int r2 = 0; r2 < 2; r2++) {
            int m = row0 + wm + mt * 16 + gid + r2 * 8;
            #pragma unroll
            for (int nt = 0; nt < 4; nt++) {
                int n = col0 + wn + nt * 8 + 2 * t4;
                if (n < N) {
                    float v0 = acc[mt][nt][r2 * 2];
                    float v1 = acc[mt][nt][r2 * 2 + 1];
                    if (MODE == 1 || MODE == 3 || MODE == 4) {
                        v0 += bias[n]; v1 += bias[n + 1];
                    }
                    if (MODE == 1) {
                        v0 = (v0 > 20.f) ? v0 : log1pf(expf(v0));
                        v1 = (v1 > 20.f) ? v1 : log1pf(expf(v1));
                    }
                    if (MODE == 3) {
                        const float kq = 0.70710678118654752f;
                        v0 = 0.5f * v0 * (1.f + erff(v0 * kq));
                        v1 = 0.5f * v1 * (1.f + erff(v1 * kq));
                    }
                    if (MODE == 2 || MODE == 4) {
                        const float* rp = resid + (size_t)m * N + n;
                        v0 += rp[0]; v1 += rp[1];
                    }
                    if (W32)
                        *(float2*)(C + (size_t)m * N + n) = make_float2(v0, v1);
                    if (W16)
                        *(__half2*)(C16 + (size_t)m * N + n) = __floats2half2_rn(v0, v1);
                }
            }
        }
    }
}

// ======================= weight conversion ==================================
struct CvtArgs {
    const float* src[6];
    __half* dst[6];
    int off[7];           // prefix offsets in float4 units
};
__global__ __launch_bounds__(256) void cvt_kernel(CvtArgs a) {
    int i = blockIdx.x * blockDim.x + threadIdx.x;
    if (i >= a.off[6]) return;
    int s = 0;
    #pragma unroll
    for (int k = 1; k < 6; k++) if (i >= a.off[k]) s = k;
    int j = i - a.off[s];
    float4 v = ((const float4*)a.src[s])[j];
    __half2* d = (__half2*)a.dst[s];
    d[2 * j]     = __floats2half2_rn(v.x, v.y);
    d[2 * j + 1] = __floats2half2_rn(v.z, v.w);
}

// ======================= LayerNorm (f16 out) ================================
__global__ __launch_bounds__(256) void ln_kernel(
    const float* __restrict__ in, __half* __restrict__ out,
    const float* __restrict__ g, const float* __restrict__ b)
{
    int row = blockIdx.x;
    const float* x = in + (size_t)row * DIM;
    float4 v = *(const float4*)(x + threadIdx.x * 4);
    float s  = v.x + v.y + v.z + v.w;
    float sq = v.x*v.x + v.y*v.y + v.z*v.z + v.w*v.w;
    #pragma unroll
    for (int o = 16; o; o >>= 1) {
        s  += __shfl_xor_sync(0xffffffffu, s,  o);
        sq += __shfl_xor_sync(0xffffffffu, sq, o);
    }
    __shared__ float ss[8], sqq[8];
    int w = threadIdx.x >> 5;
    if ((threadIdx.x & 31) == 0) { ss[w] = s; sqq[w] = sq; }
    __syncthreads();
    s = 0.f; sq = 0.f;
    #pragma unroll
    for (int i = 0; i < 8; i++) { s += ss[i]; sq += sqq[i]; }
    float mu = s * (1.0f / DIM);
    float var = sq * (1.0f / DIM) - mu * mu;
    float rs = rsqrtf(var + LN_EPS);
    float4 gg = *(const float4*)(g + threadIdx.x * 4);
    float4 bb = *(const float4*)(b + threadIdx.x * 4);
    __half2 p0 = __floats2half2_rn((v.x - mu) * rs * gg.x + bb.x,
                                   (v.y - mu) * rs * gg.y + bb.y);
    __half2 p1 = __floats2half2_rn((v.z - mu) * rs * gg.z + bb.z,
                                   (v.w - mu) * rs * gg.w + bb.w);
    __half2* o2 = (__half2*)(out + (size_t)row * DIM);
    o2[threadIdx.x * 2] = p0;
    o2[threadIdx.x * 2 + 1] = p1;
}

// ---------------- depthwise conv + SiLU -------------------------------------
__device__ __forceinline__ float silu(float v) { return v / (1.0f + expf(-v)); }

__global__ __launch_bounds__(256) void conv_silu_kernel(
    const float* __restrict__ xz,
    const float* __restrict__ wx, const float* __restrict__ bx,
    const float* __restrict__ wz, const float* __restrict__ bz,
    float* __restrict__ u, __half* __restrict__ u16, __half* __restrict__ y16)
{
    int idx = blockIdx.x * blockDim.x + threadIdx.x;
    int d = idx & (HALF - 1);
    int token = idx >> 10;
    int b = token >> 11;
    int l = token & (SEQ - 1);
    float accx = bx[d], accz = bz[d];
    #pragma unroll
    for (int k = 0; k < DCONV; k++) {
        int lp = l - 1 + k;
        if (lp >= 0 && lp < SEQ) {
            const float* row = xz + ((size_t)(b * SEQ + lp)) * DINNER;
            accx += row[d]        * wx[d * DCONV + k];
            accz += row[HALF + d] * wz[d * DCONV + k];
        }
    }
    float sx = silu(accx);
    u[(size_t)token * HALF + d] = sx;
    u16[(size_t)token * HALF + d] = __float2half(sx);
    y16[(size_t)token * DINNER + HALF + d] = __float2half(silu(accz));
}

// ---------------- selective scan (y out f16) --------------------------------
__global__ __launch_bounds__(256) void scan_kernel(
    const float* __restrict__ delta, const float* __restrict__ u,
    const float* __restrict__ xdbl, const float* __restrict__ A_log,
    const float* __restrict__ Dp, __half* __restrict__ y)
{
    int gt = blockIdx.x * blockDim.x + threadIdx.x;
    int c = gt >> 4;
    int n = gt & 15;
    int b = c >> 10;
    int d = c & (HALF - 1);

    float a  = -expf(A_log[d * DSTATE + n]);
    float Dd = Dp[d];
    float h = 0.f;

    const float* dptr = delta + (size_t)b * SEQ * HALF + d;
    const float* uptr = u     + (size_t)b * SEQ * HALF + d;
    const float* bptr = xdbl  + (size_t)b * SEQ * 96 + DTRANK + n;
    const float* cptr = xdbl  + (size_t)b * SEQ * 96 + DTRANK + DSTATE + n;
    __half* yptr = y + (size_t)b * SEQ * DINNER + d;

    float dl = dptr[0], uv = uptr[0], Bv = bptr[0], Cv = cptr[0];
    for (int t = 0; t < SEQ; t++) {
        float dl_n = dl, uv_n = uv, Bv_n = Bv, Cv_n = Cv;
        if (t + 1 < SEQ) {
            int oh = (t + 1) * HALF, o9 = (t + 1) * 96;
            dl_n = dptr[oh]; uv_n = uptr[oh];
            Bv_n = bptr[o9]; Cv_n = cptr[o9];
        }
        float dA = expf(dl * a);
        h = dA * h + (dl * Bv) * uv;
        float p = h * Cv;
        p += __shfl_xor_sync(0xffffffffu, p, 8);
        p += __shfl_xor_sync(0xffffffffu, p, 4);
        p += __shfl_xor_sync(0xffffffffu, p, 2);
        p += __shfl_xor_sync(0xffffffffu, p, 1);
        if (n == 0) yptr[(size_t)t * DINNER] = __float2half(p + uv * Dd);
        dl = dl_n; uv = uv_n; Bv = Bv_n; Cv = Cv_n;
    }
}

// ======================= launch =============================================
extern "C" void kernel_launch(void* const* d_in, const int* in_sizes, int n_in,
                              void* d_out, int out_size)
{
    const float* x         = (const float*)d_in[0];
    const float* ln1_g     = (const float*)d_in[1];
    const float* ln1_b     = (const float*)d_in[2];
    const float* in_proj_w = (const float*)d_in[3];
    const float* conv_x_w  = (const float*)d_in[4];
    const float* conv_x_b  = (const float*)d_in[5];
    const float* conv_z_w  = (const float*)d_in[6];
    const float* conv_z_b  = (const float*)d_in[7];
    const float* x_proj_w  = (const float*)d_in[8];
    const float* dt_proj_w = (const float*)d_in[9];
    const float* dt_proj_b = (const float*)d_in[10];
    const float* A_log     = (const float*)d_in[11];
    const float* Dp        = (const float*)d_in[12];
    const float* out_proj_w= (const float*)d_in[13];
    const float* ln2_g     = (const float*)d_in[14];
    const float* ln2_b     = (const float*)d_in[15];
    const float* mlp_w1    = (const float*)d_in[16];
    const float* mlp_b1    = (const float*)d_in[17];
    const float* mlp_w2    = (const float*)d_in[18];
    const float* mlp_b2    = (const float*)d_in[19];
    float* out = (float*)d_out;

    float *xz, *u, *xdbl, *delta, *res1;
    cudaGetSymbolAddress((void**)&xz,   g_xz);
    cudaGetSymbolAddress((void**)&u,    g_u);
    cudaGetSymbolAddress((void**)&xdbl, g_xdbl);
    cudaGetSymbolAddress((void**)&delta,g_delta);
    cudaGetSymbolAddress((void**)&res1, g_res1);

    __half *hln1, *hu, *hxdbl, *hy, *hln2, *hmlp;
    __half *win, *wxp, *wdt, *wout, *wm1, *wm2;
    cudaGetSymbolAddress((void**)&hln1, h_ln1);
    cudaGetSymbolAddress((void**)&hu,   h_u);
    cudaGetSymbolAddress((void**)&hxdbl,h_xdbl);
    cudaGetSymbolAddress((void**)&hy,   h_y);
    cudaGetSymbolAddress((void**)&hln2, h_ln2);
    cudaGetSymbolAddress((void**)&hmlp, h_mlp);
    cudaGetSymbolAddress((void**)&win,  w16_in);
    cudaGetSymbolAddress((void**)&wxp,  w16_xp);
    cudaGetSymbolAddress((void**)&wdt,  w16_dt);
    cudaGetSymbolAddress((void**)&wout, w16_out);
    cudaGetSymbolAddress((void**)&wm1,  w16_m1);
    cudaGetSymbolAddress((void**)&wm2,  w16_m2);

    cudaFuncSetAttribute(gemm_h<0,true,false>, cudaFuncAttributeMaxDynamicSharedMemorySize, GEMM_SMEM);
    cudaFuncSetAttribute(gemm_h<0,true,true>,  cudaFuncAttributeMaxDynamicSharedMemorySize, GEMM_SMEM);
    cudaFuncSetAttribute(gemm_h<1,true,false>, cudaFuncAttributeMaxDynamicSharedMemorySize, GEMM_SMEM);
    cudaFuncSetAttribute(gemm_h<2,true,false>, cudaFuncAttributeMaxDynamicSharedMemorySize, GEMM_SMEM);
    cudaFuncSetAttribute(gemm_h<3,false,true>, cudaFuncAttributeMaxDynamicSharedMemorySize, GEMM_SMEM);
    cudaFuncSetAttribute(gemm_h<4,true,false>, cudaFuncAttributeMaxDynamicSharedMemorySize, GEMM_SMEM);

    // 0. convert weights to f16 (float4 granularity)
    CvtArgs ca;
    ca.src[0] = in_proj_w;  ca.dst[0] = win;  int n0 = DINNER * DIM / 4;
    ca.src[1] = x_proj_w;   ca.dst[1] = wxp;  int n1 = 96 * HALF / 4;
    ca.src[2] = dt_proj_w;  ca.dst[2] = wdt;  int n2 = HALF * DTRANK / 4;
    ca.src[3] = out_proj_w; ca.dst[3] = wout; int n3 = DIM * DINNER / 4;
    ca.src[4] = mlp_w1;     ca.dst[4] = wm1;  int n4 = MLPD * DIM / 4;
    ca.src[5] = mlp_w2;     ca.dst[5] = wm2;  int n5 = DIM * MLPD / 4;
    ca.off[0] = 0;
    ca.off[1] = n0; ca.off[2] = n0+n1; ca.off[3] = n0+n1+n2;
    ca.off[4] = n0+n1+n2+n3; ca.off[5] = n0+n1+n2+n3+n4; ca.off[6] = n0+n1+n2+n3+n4+n5;
    cvt_kernel<<<(ca.off[6] + 255) / 256, 256>>>(ca);

    // 1. LN1 -> f16
    ln_kernel<<<NTOK, 256>>>(x, hln1, ln1_g, ln1_b);
    // 2. in_proj -> xz f32
    gemm_h<0,true,false><<<dim3(DINNER/128, NTOK/128), 256, GEMM_SMEM>>>(
        hln1, win, xz, nullptr, DINNER, DIM, DIM, nullptr, nullptr);
    // 3. conv + silu -> u f32 + u f16 + z f16 (into h_y right half)
    conv_silu_kernel<<<(NTOK*HALF)/256, 256>>>(xz, conv_x_w, conv_x_b,
                                               conv_z_w, conv_z_b, u, hu, hy);
    // 4. x_proj -> xdbl f32 + f16
    gemm_h<0,true,true><<<dim3(1, NTOK/128), 256, GEMM_SMEM>>>(
        hu, wxp, xdbl, hxdbl, 96, HALF, HALF, nullptr, nullptr);
    // 5. dt_proj + softplus -> delta f32
    gemm_h<1,true,false><<<dim3(HALF/128, NTOK/128), 256, GEMM_SMEM>>>(
        hxdbl, wdt, delta, nullptr, HALF, DTRANK, 96, dt_proj_b, nullptr);
    // 6. selective scan -> h_y left half (f16)
    scan_kernel<<<(BSZ*HALF*DSTATE)/256, 256>>>(delta, u, xdbl, A_log, Dp, hy);
    // 7. out_proj + residual -> res1 f32
    gemm_h<2,true,false><<<dim3(DIM/128, NTOK/128), 256, GEMM_SMEM>>>(
        hy, wout, res1, nullptr, DIM, DINNER, DINNER, nullptr, x);
    // 8. LN2 -> f16
    ln_kernel<<<NTOK, 256>>>(res1, hln2, ln2_g, ln2_b);
    // 9. mlp1 + gelu -> f16
    gemm_h<3,false,true><<<dim3(MLPD/128, NTOK/128), 256, GEMM_SMEM>>>(
        hln2, wm1, nullptr, hmlp, MLPD, DIM, DIM, mlp_b1, nullptr);
    // 10. mlp2 + bias + residual -> out f32
    gemm_h<4,true,false><<<dim3(DIM/128, NTOK/128), 256, GEMM_SMEM>>>(
        hmlp, wm2, out, nullptr, DIM, MLPD, MLPD, mlp_b2, res1);
}

// round 5
// speedup vs baseline: 3.3301x; 1.0382x over previous
#include <cuda_runtime.h>
#include <cuda_fp16.h>
#include <math.h>
#include <stdint.h>

#define DIM    1024
#define MLPD   4096
#define DSTATE 16
#define DCONV  4
#define HALF   1024
#define DINNER 2048
#define DTRANK 64
#define BSZ    2
#define SEQ    2048
#define NTOK   (BSZ * SEQ)   // 4096
#define LN_EPS 1e-5f

// ---------------- scratch (device globals) ----------------------------------
__device__ float g_xz[NTOK * DINNER];
__device__ float g_u[NTOK * HALF];
__device__ float g_xdbl[NTOK * 96];
__device__ float g_delta[NTOK * HALF];
__device__ float g_res1[NTOK * DIM];

__device__ __half h_ln1[NTOK * DIM];
__device__ __half h_u[NTOK * HALF];
__device__ __half h_xdbl[NTOK * 96];
__device__ __half h_y[NTOK * DINNER];
__device__ __half h_ln2[NTOK * DIM];
__device__ __half h_mlp[NTOK * MLPD];

__device__ __half w16_in[DINNER * DIM];
__device__ __half w16_xp[96 * HALF];
__device__ __half w16_dt[HALF * DTRANK];
__device__ __half w16_out[DIM * DINNER];
__device__ __half w16_m1[MLPD * DIM];
__device__ __half w16_m2[DIM * MLPD];

// ======================= helpers ============================================
__device__ __forceinline__ uint32_t smem_u32(const void* p) {
    uint32_t a;
    asm("{ .reg .u64 t; cvta.to.shared.u64 t, %1; cvt.u32.u64 %0, t; }"
        : "=r"(a) : "l"(p));
    return a;
}
__device__ __forceinline__ void cp16(uint32_t dst, const void* src) {
    asm volatile("cp.async.cg.shared.global [%0], [%1], 16;"
                 :: "r"(dst), "l"(src) : "memory");
}
__device__ __forceinline__ void cp16z(uint32_t dst, const void* src, int sz) {
    asm volatile("cp.async.cg.shared.global [%0], [%1], 16, %2;"
                 :: "r"(dst), "l"(src), "r"(sz) : "memory");
}
#define CP_COMMIT() asm volatile("cp.async.commit_group;" ::: "memory")
#define CP_WAIT2()  asm volatile("cp.async.wait_group 2;" ::: "memory")

__device__ __forceinline__ void lm4(uint32_t& r0, uint32_t& r1, uint32_t& r2,
                                    uint32_t& r3, uint32_t addr) {
    asm volatile("ldmatrix.sync.aligned.m8n8.x4.shared.b16 {%0,%1,%2,%3}, [%4];"
                 : "=r"(r0), "=r"(r1), "=r"(r2), "=r"(r3) : "r"(addr));
}
__device__ __forceinline__ void mma_f16(float* c, const uint32_t* a, const uint32_t* b) {
    asm volatile(
        "mma.sync.aligned.m16n8k16.row.col.f32.f16.f16.f32 "
        "{%0,%1,%2,%3}, {%4,%5,%6,%7}, {%8,%9}, {%0,%1,%2,%3};"
        : "+f"(c[0]), "+f"(c[1]), "+f"(c[2]), "+f"(c[3])
        : "r"(a[0]), "r"(a[1]), "r"(a[2]), "r"(a[3]), "r"(b[0]), "r"(b[1]));
}

// ======================= fp16 MMA GEMM ======================================
// C[M,N] = A[M,K](lda halfs) * B[N,K]^T. M%128==0, K%64==0.
// MODE 0: none  1: softplus(+bias)  2: +resid  3: gelu(+bias)  4: +bias+resid
#define PITCH_H 72                              // halfs per 64-half row (+8 pad)
#define STG_BYTES (2 * 128 * PITCH_H * 2)       // 36864
#define GEMM_SMEM (3 * STG_BYTES)               // 110592

template<int MODE, bool W32, bool W16>
__global__ __launch_bounds__(256, 2) void gemm_h(
    const __half* __restrict__ A, const __half* __restrict__ B,
    float* __restrict__ C, __half* __restrict__ C16,
    int N, int K, int lda,
    const float* __restrict__ bias, const float* __restrict__ resid)
{
    extern __shared__ char smraw[];
    const int tid = threadIdx.x;
    const int wid = tid >> 5, lane = tid & 31;
    const int gid = lane >> 2, t4 = lane & 3;
    const int wm = (wid >> 2) * 64, wn = (wid & 3) * 32;
    const int row0 = blockIdx.y * 128, col0 = blockIdx.x * 128;
    const int NC = K >> 6;                      // K chunks of 64
    uint32_t sbase = smem_u32(smraw);

    auto load_chunk = [&](int c, int s) {
        uint32_t As = sbase + (uint32_t)s * STG_BYTES;
        uint32_t Bs = As + 128 * PITCH_H * 2;
        int k0 = c * 64;
        #pragma unroll
        for (int i = 0; i < 4; i++) {
            int idx = tid + 256 * i;
            int r = idx >> 3, c8 = (idx & 7) * 8;
            cp16(As + (uint32_t)(r * PITCH_H + c8) * 2,
                 A + (size_t)(row0 + r) * lda + k0 + c8);
        }
        #pragma unroll
        for (int i = 0; i < 4; i++) {
            int idx = tid + 256 * i;
            int r = idx >> 3, c8 = (idx & 7) * 8;
            int brow = col0 + r;
            const __half* src = B + (size_t)(brow < N ? brow : 0) * K + k0 + c8;
            cp16z(Bs + (uint32_t)(r * PITCH_H + c8) * 2, src, brow < N ? 16 : 0);
        }
    };

    float acc[4][4][4];
    #pragma unroll
    for (int i = 0; i < 4; i++)
        #pragma unroll
        for (int j = 0; j < 4; j++)
            #pragma unroll
            for (int q = 0; q < 4; q++) acc[i][j][q] = 0.f;

    #pragma unroll
    for (int c = 0; c < 2; c++) {
        if (c < NC) load_chunk(c, c);
        CP_COMMIT();
    }

    // per-lane fragment base addresses (byte offsets within a stage)
    const uint32_t aoff = (uint32_t)((wm + (lane & 15)) * PITCH_H + ((lane >> 4) << 3)) * 2;
    const uint32_t boff = 128 * PITCH_H * 2 +
        (uint32_t)((wn + ((lane >> 4) << 3) + (lane & 7)) * PITCH_H + (((lane >> 3) & 1) << 3)) * 2;

    for (int c = 0; c < NC; c++) {
        if (c + 2 < NC) load_chunk(c + 2, (c + 2) % 3);
        CP_COMMIT();
        CP_WAIT2();
        __syncthreads();

        uint32_t stage = sbase + (uint32_t)(c % 3) * STG_BYTES;
        #pragma unroll
        for (int k16 = 0; k16 < 4; k16++) {
            uint32_t kb = (uint32_t)(k16 * 16) * 2;
            uint32_t af[4][4], bf[4][2];
            #pragma unroll
            for (int mt = 0; mt < 4; mt++)
                lm4(af[mt][0], af[mt][1], af[mt][2], af[mt][3],
                    stage + aoff + kb + (uint32_t)(mt * 16 * PITCH_H) * 2);
            #pragma unroll
            for (int np = 0; np < 2; np++)
                lm4(bf[2*np][0], bf[2*np][1], bf[2*np+1][0], bf[2*np+1][1],
                    stage + boff + kb + (uint32_t)(np * 16 * PITCH_H) * 2);
            #pragma unroll
            for (int mt = 0; mt < 4; mt++)
                #pragma unroll
                for (int nt = 0; nt < 4; nt++)
                    mma_f16(acc[mt][nt], af[mt], bf[nt]);
        }
        __syncthreads();
    }

    // ---- epilogue ------------------------------------------------------
    #pragma unroll
    for (int mt = 0; mt < 4; mt++) {
        #pragma unroll
        for (int r2 = 0; r2 < 2; r2++) {
            int m = row0 + wm + mt * 16 + gid + r2 * 8;
            #pragma unroll
            for (int nt = 0; nt < 4; nt++) {
                int n = col0 + wn + nt * 8 + 2 * t4;
                if (n < N) {
                    float v0 = acc[mt][nt][r2 * 2];
                    float v1 = acc[mt][nt][r2 * 2 + 1];
                    if (MODE == 1 || MODE == 3 || MODE == 4) {
                        v0 += bias[n]; v1 += bias[n + 1];
                    }
                    if (MODE == 1) {
                        v0 = (v0 > 20.f) ? v0 : log1pf(expf(v0));
                        v1 = (v1 > 20.f) ? v1 : log1pf(expf(v1));
                    }
                    if (MODE == 3) {
                        const float kq = 0.70710678118654752f;
                        v0 = 0.5f * v0 * (1.f + erff(v0 * kq));
                        v1 = 0.5f * v1 * (1.f + erff(v1 * kq));
                    }
                    if (MODE == 2 || MODE == 4) {
                        const float* rp = resid + (size_t)m * N + n;
                        v0 += rp[0]; v1 += rp[1];
                    }
                    if (W32)
                        *(float2*)(C + (size_t)m * N + n) = make_float2(v0, v1);
                    if (W16)
                        *(__half2*)(C16 + (size_t)m * N + n) = __floats2half2_rn(v0, v1);
                }
            }
        }
    }
}

// ======================= weight conversion ==================================
struct CvtArgs {
    const float* src[6];
    __half* dst[6];
    int off[7];           // prefix offsets in float4 units
};
__global__ __launch_bounds__(256) void cvt_kernel(CvtArgs a) {
    int i = blockIdx.x * blockDim.x + threadIdx.x;
    if (i >= a.off[6]) return;
    int s = 0;
    #pragma unroll
    for (int k = 1; k < 6; k++) if (i >= a.off[k]) s = k;
    int j = i - a.off[s];
    float4 v = ((const float4*)a.src[s])[j];
    __half2* d = (__half2*)a.dst[s];
    d[2 * j]     = __floats2half2_rn(v.x, v.y);
    d[2 * j + 1] = __floats2half2_rn(v.z, v.w);
}

// ======================= LayerNorm (f16 out) ================================
__global__ __launch_bounds__(256) void ln_kernel(
    const float* __restrict__ in, __half* __restrict__ out,
    const float* __restrict__ g, const float* __restrict__ b)
{
    int row = blockIdx.x;
    const float* x = in + (size_t)row * DIM;
    float4 v = *(const float4*)(x + threadIdx.x * 4);
    float s  = v.x + v.y + v.z + v.w;
    float sq = v.x*v.x + v.y*v.y + v.z*v.z + v.w*v.w;
    #pragma unroll
    for (int o = 16; o; o >>= 1) {
        s  += __shfl_xor_sync(0xffffffffu, s,  o);
        sq += __shfl_xor_sync(0xffffffffu, sq, o);
    }
    __shared__ float ss[8], sqq[8];
    int w = threadIdx.x >> 5;
    if ((threadIdx.x & 31) == 0) { ss[w] = s; sqq[w] = sq; }
    __syncthreads();
    s = 0.f; sq = 0.f;
    #pragma unroll
    for (int i = 0; i < 8; i++) { s += ss[i]; sq += sqq[i]; }
    float mu = s * (1.0f / DIM);
    float var = sq * (1.0f / DIM) - mu * mu;
    float rs = rsqrtf(var + LN_EPS);
    float4 gg = *(const float4*)(g + threadIdx.x * 4);
    float4 bb = *(const float4*)(b + threadIdx.x * 4);
    __half2 p0 = __floats2half2_rn((v.x - mu) * rs * gg.x + bb.x,
                                   (v.y - mu) * rs * gg.y + bb.y);
    __half2 p1 = __floats2half2_rn((v.z - mu) * rs * gg.z + bb.z,
                                   (v.w - mu) * rs * gg.w + bb.w);
    __half2* o2 = (__half2*)(out + (size_t)row * DIM);
    o2[threadIdx.x * 2] = p0;
    o2[threadIdx.x * 2 + 1] = p1;
}

// ---------------- depthwise conv + SiLU -------------------------------------
__device__ __forceinline__ float silu(float v) { return v / (1.0f + expf(-v)); }

__global__ __launch_bounds__(256) void conv_silu_kernel(
    const float* __restrict__ xz,
    const float* __restrict__ wx, const float* __restrict__ bx,
    const float* __restrict__ wz, const float* __restrict__ bz,
    float* __restrict__ u, __half* __restrict__ u16, __half* __restrict__ y16)
{
    int idx = blockIdx.x * blockDim.x + threadIdx.x;
    int d = idx & (HALF - 1);
    int token = idx >> 10;
    int b = token >> 11;
    int l = token & (SEQ - 1);
    float accx = bx[d], accz = bz[d];
    #pragma unroll
    for (int k = 0; k < DCONV; k++) {
        int lp = l - 1 + k;
        if (lp >= 0 && lp < SEQ) {
            const float* row = xz + ((size_t)(b * SEQ + lp)) * DINNER;
            accx += row[d]        * wx[d * DCONV + k];
            accz += row[HALF + d] * wz[d * DCONV + k];
        }
    }
    float sx = silu(accx);
    u[(size_t)token * HALF + d] = sx;
    u16[(size_t)token * HALF + d] = __float2half(sx);
    y16[(size_t)token * DINNER + HALF + d] = __float2half(silu(accz));
}

// ---------------- selective scan (y out f16) --------------------------------
__global__ __launch_bounds__(256) void scan_kernel(
    const float* __restrict__ delta, const float* __restrict__ u,
    const float* __restrict__ xdbl, const float* __restrict__ A_log,
    const float* __restrict__ Dp, __half* __restrict__ y)
{
    int gt = blockIdx.x * blockDim.x + threadIdx.x;
    int c = gt >> 4;
    int n = gt & 15;
    int b = c >> 10;
    int d = c & (HALF - 1);

    float a  = -expf(A_log[d * DSTATE + n]);
    float Dd = Dp[d];
    float h = 0.f;

    const float* dptr = delta + (size_t)b * SEQ * HALF + d;
    const float* uptr = u     + (size_t)b * SEQ * HALF + d;
    const float* bptr = xdbl  + (size_t)b * SEQ * 96 + DTRANK + n;
    const float* cptr = xdbl  + (size_t)b * SEQ * 96 + DTRANK + DSTATE + n;
    __half* yptr = y + (size_t)b * SEQ * DINNER + d;

    float dl = dptr[0], uv = uptr[0], Bv = bptr[0], Cv = cptr[0];
    for (int t = 0; t < SEQ; t++) {
        float dl_n = dl, uv_n = uv, Bv_n = Bv, Cv_n = Cv;
        if (t + 1 < SEQ) {
            int oh = (t + 1) * HALF, o9 = (t + 1) * 96;
            dl_n = dptr[oh]; uv_n = uptr[oh];
            Bv_n = bptr[o9]; Cv_n = cptr[o9];
        }
        float dA = expf(dl * a);
        h = dA * h + (dl * Bv) * uv;
        float p = h * Cv;
        p += __shfl_xor_sync(0xffffffffu, p, 8);
        p += __shfl_xor_sync(0xffffffffu, p, 4);
        p += __shfl_xor_sync(0xffffffffu, p, 2);
        p += __shfl_xor_sync(0xffffffffu, p, 1);
        if (n == 0) yptr[(size_t)t * DINNER] = __float2half(p + uv * Dd);
        dl = dl_n; uv = uv_n; Bv = Bv_n; Cv = Cv_n;
    }
}

// ======================= launch =============================================
extern "C" void kernel_launch(void* const* d_in, const int* in_sizes, int n_in,
                              void* d_out, int out_size)
{
    const float* x         = (const float*)d_in[0];
    const float* ln1_g     = (const float*)d_in[1];
    const float* ln1_b     = (const float*)d_in[2];
    const float* in_proj_w = (const float*)d_in[3];
    const float* conv_x_w  = (const float*)d_in[4];
    const float* conv_x_b  = (const float*)d_in[5];
    const float* conv_z_w  = (const float*)d_in[6];
    const float* conv_z_b  = (const float*)d_in[7];
    const float* x_proj_w  = (const float*)d_in[8];
    const float* dt_proj_w = (const float*)d_in[9];
    const float* dt_proj_b = (const float*)d_in[10];
    const float* A_log     = (const float*)d_in[11];
    const float* Dp        = (const float*)d_in[12];
    const float* out_proj_w= (const float*)d_in[13];
    const float* ln2_g     = (const float*)d_in[14];
    const float* ln2_b     = (const float*)d_in[15];
    const float* mlp_w1    = (const float*)d_in[16];
    const float* mlp_b1    = (const float*)d_in[17];
    const float* mlp_w2    = (const float*)d_in[18];
    const float* mlp_b2    = (const float*)d_in[19];
    float* out = (float*)d_out;

    float *xz, *u, *xdbl, *delta, *res1;
    cudaGetSymbolAddress((void**)&xz,   g_xz);
    cudaGetSymbolAddress((void**)&u,    g_u);
    cudaGetSymbolAddress((void**)&xdbl, g_xdbl);
    cudaGetSymbolAddress((void**)&delta,g_delta);
    cudaGetSymbolAddress((void**)&res1, g_res1);

    __half *hln1, *hu, *hxdbl, *hy, *hln2, *hmlp;
    __half *win, *wxp, *wdt, *wout, *wm1, *wm2;
    cudaGetSymbolAddress((void**)&hln1, h_ln1);
    cudaGetSymbolAddress((void**)&hu,   h_u);
    cudaGetSymbolAddress((void**)&hxdbl,h_xdbl);
    cudaGetSymbolAddress((void**)&hy,   h_y);
    cudaGetSymbolAddress((void**)&hln2, h_ln2);
    cudaGetSymbolAddress((void**)&hmlp, h_mlp);
    cudaGetSymbolAddress((void**)&win,  w16_in);
    cudaGetSymbolAddress((void**)&wxp,  w16_xp);
    cudaGetSymbolAddress((void**)&wdt,  w16_dt);
    cudaGetSymbolAddress((void**)&wout, w16_out);
    cudaGetSymbolAddress((void**)&wm1,  w16_m1);
    cudaGetSymbolAddress((void**)&wm2,  w16_m2);

    cudaFuncSetAttribute(gemm_h<0,true,false>, cudaFuncAttributeMaxDynamicSharedMemorySize, GEMM_SMEM);
    cudaFuncSetAttribute(gemm_h<0,true,true>,  cudaFuncAttributeMaxDynamicSharedMemorySize, GEMM_SMEM);
    cudaFuncSetAttribute(gemm_h<1,true,false>, cudaFuncAttributeMaxDynamicSharedMemorySize, GEMM_SMEM);
    cudaFuncSetAttribute(gemm_h<2,true,false>, cudaFuncAttributeMaxDynamicSharedMemorySize, GEMM_SMEM);
    cudaFuncSetAttribute(gemm_h<3,false,true>, cudaFuncAttributeMaxDynamicSharedMemorySize, GEMM_SMEM);
    cudaFuncSetAttribute(gemm_h<4,true,false>, cudaFuncAttributeMaxDynamicSharedMemorySize, GEMM_SMEM);

    // 0. convert weights to f16 (float4 granularity)
    CvtArgs ca;
    ca.src[0] = in_proj_w;  ca.dst[0] = win;  int n0 = DINNER * DIM / 4;
    ca.src[1] = x_proj_w;   ca.dst[1] = wxp;  int n1 = 96 * HALF / 4;
    ca.src[2] = dt_proj_w;  ca.dst[2] = wdt;  int n2 = HALF * DTRANK / 4;
    ca.src[3] = out_proj_w; ca.dst[3] = wout; int n3 = DIM * DINNER / 4;
    ca.src[4] = mlp_w1;     ca.dst[4] = wm1;  int n4 = MLPD * DIM / 4;
    ca.src[5] = mlp_w2;     ca.dst[5] = wm2;  int n5 = DIM * MLPD / 4;
    ca.off[0] = 0;
    ca.off[1] = n0; ca.off[2] = n0+n1; ca.off[3] = n0+n1+n2;
    ca.off[4] = n0+n1+n2+n3; ca.off[5] = n0+n1+n2+n3+n4; ca.off[6] = n0+n1+n2+n3+n4+n5;
    cvt_kernel<<<(ca.off[6] + 255) / 256, 256>>>(ca);

    // 1. LN1 -> f16
    ln_kernel<<<NTOK, 256>>>(x, hln1, ln1_g, ln1_b);
    // 2. in_proj -> xz f32
    gemm_h<0,true,false><<<dim3(DINNER/128, NTOK/128), 256, GEMM_SMEM>>>(
        hln1, win, xz, nullptr, DINNER, DIM, DIM, nullptr, nullptr);
    // 3. conv + silu -> u f32 + u f16 + z f16 (into h_y right half)
    conv_silu_kernel<<<(NTOK*HALF)/256, 256>>>(xz, conv_x_w, conv_x_b,
                                               conv_z_w, conv_z_b, u, hu, hy);
    // 4. x_proj -> xdbl f32 + f16
    gemm_h<0,true,true><<<dim3(1, NTOK/128), 256, GEMM_SMEM>>>(
        hu, wxp, xdbl, hxdbl, 96, HALF, HALF, nullptr, nullptr);
    // 5. dt_proj + softplus -> delta f32
    gemm_h<1,true,false><<<dim3(HALF/128, NTOK/128), 256, GEMM_SMEM>>>(
        hxdbl, wdt, delta, nullptr, HALF, DTRANK, 96, dt_proj_b, nullptr);
    // 6. selective scan -> h_y left half (f16)
    scan_kernel<<<(BSZ*HALF*DSTATE)/256, 256>>>(delta, u, xdbl, A_log, Dp, hy);
    // 7. out_proj + residual -> res1 f32
    gemm_h<2,true,false><<<dim3(DIM/128, NTOK/128), 256, GEMM_SMEM>>>(
        hy, wout, res1, nullptr, DIM, DINNER, DINNER, nullptr, x);
    // 8. LN2 -> f16
    ln_kernel<<<NTOK, 256>>>(res1, hln2, ln2_g, ln2_b);
    // 9. mlp1 + gelu -> f16
    gemm_h<3,false,true><<<dim3(MLPD/128, NTOK/128), 256, GEMM_SMEM>>>(
        hln2, wm1, nullptr, hmlp, MLPD, DIM, DIM, mlp_b1, nullptr);
    // 10. mlp2 + bias + residual -> out f32
    gemm_h<4,true,false><<<dim3(DIM/128, NTOK/128), 256, GEMM_SMEM>>>(
        hmlp, wm2, out, nullptr, DIM, MLPD, MLPD, mlp_b2, res1);
}